// round 5
// baseline (speedup 1.0000x reference)
#include <cuda_runtime.h>
#include <cuda_bf16.h>
#include <cstdint>

#define NUM_TAGS 32
#define START_TAG 30
#define STOP_TAG 31
#define MAX_B 1024
#define SEQ_S 512
#define LN2F 0.6931471805599453f

__device__ float g_partial[MAX_B];
__device__ unsigned g_done = 0;

__device__ __forceinline__ unsigned long long fma2(unsigned long long a,
                                                   unsigned long long b,
                                                   unsigned long long c) {
    unsigned long long d;
    asm("fma.rn.f32x2 %0, %1, %2, %3;" : "=l"(d) : "l"(a), "l"(b), "l"(c));
    return d;
}
__device__ __forceinline__ unsigned long long mul2(unsigned long long a,
                                                   unsigned long long b) {
    unsigned long long d;
    asm("mul.rn.f32x2 %0, %1, %2;" : "=l"(d) : "l"(a), "l"(b));
    return d;
}
__device__ __forceinline__ unsigned long long add2(unsigned long long a,
                                                   unsigned long long b) {
    unsigned long long d;
    asm("add.rn.f32x2 %0, %1, %2;" : "=l"(d) : "l"(a), "l"(b));
    return d;
}
__device__ __forceinline__ void unpack2(unsigned long long v, float& lo, float& hi) {
    asm("mov.b64 {%0, %1}, %2;" : "=f"(lo), "=f"(hi) : "l"(v));
}
__device__ __forceinline__ unsigned long long pack2(float lo, float hi) {
    unsigned long long v;
    asm("mov.b64 %0, {%1, %2};" : "=l"(v) : "f"(lo), "f"(hi));
    return v;
}
// Ordered same-warp smem ops; loop body is fully convergent (masks are
// warp-uniform), so no warp sync is needed between ST and LD.
__device__ __forceinline__ void sts32(uint32_t addr, float v) {
    asm volatile("st.shared.b32 [%0], %1;" :: "r"(addr), "f"(v) : "memory");
}
__device__ __forceinline__ ulonglong2 lds128(uint32_t addr) {
    ulonglong2 r;
    asm volatile("ld.shared.v2.b64 {%0, %1}, [%2];"
                 : "=l"(r.x), "=l"(r.y) : "r"(addr));
    return r;
}

// 4 warps per block (one per SMSP), one batch per warp.
__global__ __launch_bounds__(128) void crf_forward_kernel(
    const float* __restrict__ feats,       // [B, 512, 32]
    const int*   __restrict__ labels,      // [B, 512]
    const int*   __restrict__ lengths,     // [B]
    const float* __restrict__ transitions, // [32, 32]
    float* __restrict__ out, int B, int nblocks)
{
    __shared__ float sT[NUM_TAGS * NUM_TAGS];
    __shared__ float sAlpha[4][2][NUM_TAGS];   // [warp][parity][tag]
    __shared__ float sred[128];
    __shared__ int sIsLast;

    const int tid  = threadIdx.x;
    const int w    = tid >> 5;
    const int lane = tid & 31;

    #pragma unroll
    for (int k = 0; k < 8; k++)
        sT[tid + k * 128] = transitions[tid + k * 128];
    __syncthreads();

    const int b = blockIdx.x * 4 + w;

    if (b < B) {
        // Packed E columns: Epk[q] = ( exp(T[2q][lane]), exp(T[2q+1][lane]) )
        unsigned long long Epk[16];
        #pragma unroll
        for (int q = 0; q < 16; q++) {
            float e0 = __expf(sT[(2 * q) * NUM_TAGS + lane]);
            float e1 = __expf(sT[(2 * q + 1) * NUM_TAGS + lane]);
            Epk[q] = pack2(e0, e1);
        }

        const int len = lengths[b];
        const float* fb = feats + (size_t)b * SEQ_S * NUM_TAGS;
        const int labBase = b * SEQ_S;

        const uint32_t a0 = (uint32_t)__cvta_generic_to_shared(&sAlpha[w][0][0]);
        const uint32_t a1 = (uint32_t)__cvta_generic_to_shared(&sAlpha[w][1][0]);
        const uint32_t wr0 = a0 + lane * 4;
        const uint32_t wr1 = a1 + lane * 4;

        // Prologue rows 1..7 and first superblock rows 8..15
        float fpre[7], fX[8], fY[8];
        #pragma unroll
        for (int d = 0; d < 7; d++) fpre[d] = fb[(1 + d) * NUM_TAGS + lane];
        #pragma unroll
        for (int d = 0; d < 8; d++) fX[d] = fb[(8 + d) * NUM_TAGS + lane];

        const float f0 = fb[lane];
        float alpha = __expf(f0 + sT[START_TAG * NUM_TAGS + lane]);
        int ilog = 0;
        unsigned prev_mb = 127u << 23;   // "no scale" seed

// 4 chained accumulators: 4 mul2 + 12 fma2 + 3 add2 = 19 packed fma-pipe ops.
#define CRF_STEP(WRA, RDA, EF, VALID)                                         \
    {                                                                          \
        sts32((WRA), alpha);                                                   \
        ulonglong2 q0 = lds128((RDA));       ulonglong2 q1 = lds128((RDA)+16); \
        ulonglong2 q2 = lds128((RDA)+32);    ulonglong2 q3 = lds128((RDA)+48); \
        ulonglong2 q4 = lds128((RDA)+64);    ulonglong2 q5 = lds128((RDA)+80); \
        ulonglong2 q6 = lds128((RDA)+96);    ulonglong2 q7 = lds128((RDA)+112);\
        unsigned long long c0 = mul2(q0.x, Epk[0]);                            \
        unsigned long long c1 = mul2(q0.y, Epk[1]);                            \
        unsigned long long c2 = mul2(q1.x, Epk[2]);                            \
        unsigned long long c3 = mul2(q1.y, Epk[3]);                            \
        c0 = fma2(q2.x, Epk[4],  c0);                                          \
        c1 = fma2(q2.y, Epk[5],  c1);                                          \
        c2 = fma2(q3.x, Epk[6],  c2);                                          \
        c3 = fma2(q3.y, Epk[7],  c3);                                          \
        c0 = fma2(q4.x, Epk[8],  c0);                                          \
        c1 = fma2(q4.y, Epk[9],  c1);                                          \
        c2 = fma2(q5.x, Epk[10], c2);                                          \
        c3 = fma2(q5.y, Epk[11], c3);                                          \
        c0 = fma2(q6.x, Epk[12], c0);                                          \
        c1 = fma2(q6.y, Epk[13], c1);                                          \
        c2 = fma2(q7.x, Epk[14], c2);                                          \
        c3 = fma2(q7.y, Epk[15], c3);                                          \
        c0 = add2(c0, c1); c2 = add2(c2, c3); c0 = add2(c0, c2);               \
        float lo_, hi_; unpack2(c0, lo_, hi_);                                 \
        const float an_ = (lo_ + hi_) * (EF);                                  \
        alpha = (VALID) ? an_ : alpha;                                         \
    }

#define CRF_RENORM                                                             \
    {                                                                          \
        int e_ = (int)((prev_mb >> 23) & 0xff);                                \
        int sc_ = 254 - e_; sc_ = (sc_ < 1) ? 1 : sc_;                         \
        sc_ = (sc_ > 254) ? 254 : sc_;                                         \
        alpha *= __int_as_float(sc_ << 23);                                    \
        ilog += 127 - sc_;                                                     \
        prev_mb = __reduce_max_sync(0xffffffffu, __float_as_uint(alpha));      \
    }

// One 8-step superblock starting at t (warp-uniform): prefetch next 8 rows
// into NXT, run 8 masked steps from CUR, renorm once.
#define CRF_SUPER(CUR, NXT, TBASE)                                             \
    {                                                                          \
        _Pragma("unroll")                                                      \
        for (int u = 0; u < 8; u++) {                                          \
            int r_ = (TBASE) + 8 + u; r_ = (r_ < SEQ_S) ? r_ : (SEQ_S - 1);    \
            NXT[u] = fb[r_ * NUM_TAGS + lane];                                 \
        }                                                                      \
        _Pragma("unroll")                                                      \
        for (int u = 0; u < 8; u++) {                                          \
            const int t_ = (TBASE) + u;                                        \
            const float ef_ = __expf(CUR[u]);                                  \
            const uint32_t wrad = (t_ & 1) ? wr1 : wr0;                        \
            const uint32_t rdad = (t_ & 1) ? a1 : a0;                          \
            CRF_STEP(wrad, rdad, ef_, t_ < len);                               \
        }                                                                      \
        CRF_RENORM;                                                            \
    }

        // Prologue: masked steps t = 1..7
        #pragma unroll
        for (int u = 0; u < 7; u++) {
            const int t_ = 1 + u;
            const float ef_ = __expf(fpre[u]);
            const uint32_t wrad = (t_ & 1) ? wr1 : wr0;
            const uint32_t rdad = (t_ & 1) ? a1 : a0;
            CRF_STEP(wrad, rdad, ef_, t_ < len);
        }
        CRF_RENORM;

        // Main loop: ping-pong superblocks (no buffer copies)
        int t = 8;
        while (t < len) {
            CRF_SUPER(fX, fY, t);
            t += 8;
            if (t >= len) break;
            CRF_SUPER(fY, fX, t);
            t += 8;
        }
#undef CRF_STEP
#undef CRF_RENORM
#undef CRF_SUPER

        // Gold score epilogue (order-independent, latency tolerant)
        float epacc = 0.0f;
        for (int base = 0; base < len; base += 32) {
            const int pos = base + lane;
            const bool v = pos < len;
            const int cp = v ? pos : (len - 1);
            const int lab = labels[labBase + cp];
            const float fv = fb[cp * NUM_TAGS + lab];
            float contrib = fv;
            if (pos >= 1) {
                const int lp = labels[labBase + cp - 1];
                contrib += sT[lp * NUM_TAGS + lab];
            }
            if (v) epacc += contrib;
        }

        float total = alpha;
        #pragma unroll
        for (int off = 16; off >= 1; off >>= 1) {
            total += __shfl_xor_sync(0xffffffffu, total, off);
            epacc += __shfl_xor_sync(0xffffffffu, epacc, off);
        }
        const float fwd = __logf(total) + (float)ilog * LN2F;

        const int lab0 = labels[labBase];
        const int labL = labels[labBase + len - 1];
        const float gold = epacc + sT[START_TAG * NUM_TAGS + lab0]
                                 + sT[labL * NUM_TAGS + STOP_TAG];

        if (lane == 0) g_partial[b] = fwd - gold;
    }

    // Fused final reduction: last block to finish sums all partials.
    __syncthreads();
    if (tid == 0) {
        __threadfence();
        unsigned r = atomicAdd(&g_done, 1u);
        sIsLast = (r == (unsigned)(nblocks - 1));
    }
    __syncthreads();
    if (sIsLast) {
        __threadfence();
        float s = 0.0f;
        for (int i = tid; i < B; i += 128) s += g_partial[i];
        sred[tid] = s;
        __syncthreads();
        if (tid < 64) sred[tid] += sred[tid + 64];
        __syncthreads();
        if (tid < 32) {
            float v2 = sred[tid] + sred[tid + 32];
            #pragma unroll
            for (int off = 16; off >= 1; off >>= 1)
                v2 += __shfl_xor_sync(0xffffffffu, v2, off);
            if (tid == 0) {
                out[0] = v2 / (float)B;
                g_done = 0;   // reset for next graph replay
            }
        }
    }
}

extern "C" void kernel_launch(void* const* d_in, const int* in_sizes, int n_in,
                              void* d_out, int out_size)
{
    const float* feats       = (const float*)d_in[0];
    const int*   labels      = (const int*)d_in[1];
    const int*   lengths     = (const int*)d_in[2];
    const float* transitions = (const float*)d_in[3];
    float* out = (float*)d_out;

    const int B = in_sizes[2];
    const int blocks = (B + 3) / 4;   // 4 warps/block, one batch per warp

    crf_forward_kernel<<<blocks, 128>>>(feats, labels, lengths, transitions,
                                        out, B, blocks);
}